// round 5
// baseline (speedup 1.0000x reference)
#include <cuda_runtime.h>
#include <cuda.h>
#include <cstdint>

#define DIM         2048
#define NEXP        8
#define TILE_T      64
#define WARPS       8
#define THREADS     256
#define STAGE_COLS  64
#define NSTAGES     (DIM / STAGE_COLS)      // 32
#define NBUF        6
#define SUB_BYTES   8192                    // one TMA box: 32 f32 x 64 tokens
#define STAGE_BYTES 16384                   // two boxes
#define BARS_OFF    (NBUF * STAGE_BYTES)    // 98304
#define SMEM_TOTAL  (BARS_OFF + NBUF * 16)
#define MOE_COEFF   0.01f
#define MAX_BLOCKS  1024

__device__ float        g_imp_part[MAX_BLOCKS * NEXP];
__device__ float        g_load_part[MAX_BLOCKS * NEXP];
__device__ unsigned int g_ticket = 0;

__device__ __forceinline__ unsigned long long ffma2(unsigned long long a,
                                                    unsigned long long b,
                                                    unsigned long long c) {
    unsigned long long d;
    asm("fma.rn.f32x2 %0, %1, %2, %3;" : "=l"(d) : "l"(a), "l"(b), "l"(c));
    return d;
}
__device__ __forceinline__ unsigned long long pack2(float x, float y) {
    unsigned long long d;
    asm("mov.b64 %0, {%1, %2};" : "=l"(d) : "f"(x), "f"(y));
    return d;
}
__device__ __forceinline__ float2 unpack2(unsigned long long d) {
    float2 r;
    asm("mov.b64 {%0, %1}, %2;" : "=f"(r.x), "=f"(r.y) : "l"(d));
    return r;
}
__device__ __forceinline__ void mbar_init(unsigned int a, unsigned int cnt) {
    asm volatile("mbarrier.init.shared.b64 [%0], %1;" :: "r"(a), "r"(cnt) : "memory");
}
__device__ __forceinline__ void mbar_arrive(unsigned int a) {
    asm volatile("mbarrier.arrive.shared.b64 _, [%0];" :: "r"(a) : "memory");
}
__device__ __forceinline__ void mbar_expect_tx(unsigned int a, unsigned int bytes) {
    asm volatile("mbarrier.arrive.expect_tx.shared.b64 _, [%0], %1;"
                 :: "r"(a), "r"(bytes) : "memory");
}
__device__ __forceinline__ void mbar_wait_acq(unsigned int a, unsigned int parity) {
    asm volatile(
        "{\n\t.reg .pred P1;\n\t"
        "WL_%=:\n\t"
        "mbarrier.try_wait.parity.acquire.cta.shared::cta.b64 P1, [%0], %1, 0x989680;\n\t"
        "@P1 bra.uni WD_%=;\n\t"
        "bra.uni WL_%=;\n\t"
        "WD_%=:\n\t}"
        :: "r"(a), "r"(parity) : "memory");
}
__device__ __forceinline__ void mbar_wait_rel(unsigned int a, unsigned int parity) {
    asm volatile(
        "{\n\t.reg .pred P1;\n\t"
        "WL_%=:\n\t"
        "mbarrier.try_wait.parity.relaxed.cta.shared::cta.b64 P1, [%0], %1, 0x989680;\n\t"
        "@P1 bra.uni WD_%=;\n\t"
        "bra.uni WL_%=;\n\t"
        "WD_%=:\n\t}"
        :: "r"(a), "r"(parity) : "memory");
}
__device__ __forceinline__ void tma2d(unsigned int dst, const CUtensorMap* tm,
                                      int cx, int cy, unsigned int mbar) {
    asm volatile(
        "cp.async.bulk.tensor.2d.shared::cta.global.tile.mbarrier::complete_tx::bytes "
        "[%0], [%1, {%2, %3}], [%4];"
        :: "r"(dst), "l"(tm), "r"(cx), "r"(cy), "r"(mbar) : "memory");
}

__global__ void __launch_bounds__(THREADS)
gate_kernel(const __grid_constant__ CUtensorMap tmap,
            const float* __restrict__ W, float* __restrict__ out,
            int half, int ntok, int auxPos) {
    extern __shared__ char smem[];
    const unsigned int sbase = (unsigned int)__cvta_generic_to_shared(smem);
    float* logitsBuf = reinterpret_cast<float*>(smem);  // union over staging

    const int tid  = threadIdx.x;
    const int w    = tid >> 5;
    const int lane = tid & 31;
    const int tok0 = blockIdx.x * TILE_T;

    const unsigned int fullBar0  = sbase + BARS_OFF;
    const unsigned int emptyBar0 = sbase + BARS_OFF + 8;

    if (tid == 0) {
        #pragma unroll
        for (int i = 0; i < NBUF; i++) {
            mbar_init(fullBar0 + i * 16, 1);        // one expect_tx arrival
            mbar_init(emptyBar0 + i * 16, THREADS); // all threads arrive
        }
    }
    __syncthreads();

    #define PRODUCE(t)                                                          \
    {                                                                           \
        const int bi_ = (t) % NBUF;                                             \
        mbar_wait_rel(emptyBar0 + bi_ * 16, 1u ^ (((t) / NBUF) & 1u));          \
        mbar_expect_tx(fullBar0 + bi_ * 16, STAGE_BYTES);                       \
        const unsigned int d0_ = sbase + bi_ * STAGE_BYTES;                     \
        tma2d(d0_, &tmap, (t) * STAGE_COLS, tok0, fullBar0 + bi_ * 16);         \
        tma2d(d0_ + SUB_BYTES, &tmap, (t) * STAGE_COLS + 32, tok0,              \
              fullBar0 + bi_ * 16);                                             \
    }

    if (tid == 0) {
        #pragma unroll
        for (int t = 0; t < NBUF - 1; t++) PRODUCE(t);
    }

    unsigned long long accA[NEXP], accB[NEXP];
    #pragma unroll
    for (int e = 0; e < NEXP; e++) { accA[e] = 0ULL; accB[e] = 0ULL; }

    const float4* W4 = reinterpret_cast<const float4*>(W);
    // warp w owns cols [s*64 + w*8, +8); sub-tile: w<4 -> first box, w>=4 -> second
    const int subOff = (w >= 4) ? SUB_BYTES : 0;
    const int pi     = (w & 3) * 2;              // 16B-piece index within 128B row
    const int rot    = lane & 7;                 // (lane+32)&7 == lane&7
    const int offA0 = lane * 128 + ((pi     ^ rot) * 16);
    const int offA1 = lane * 128 + (((pi+1) ^ rot) * 16);
    const int offB0 = (lane + 32) * 128 + ((pi     ^ rot) * 16);
    const int offB1 = (lane + 32) * 128 + (((pi+1) ^ rot) * 16);

    #pragma unroll 1
    for (int s = 0; s < NSTAGES; s++) {
        if (tid == 0) {
            const int t = s + NBUF - 1;
            if (t < NSTAGES) PRODUCE(t);
        }
        const int bi = s % NBUF;
        mbar_wait_acq(fullBar0 + bi * 16, (s / NBUF) & 1);

        const char* sub = smem + bi * STAGE_BYTES + subOff;
        float4 a0 = *reinterpret_cast<const float4*>(sub + offA0);
        float4 a1 = *reinterpret_cast<const float4*>(sub + offA1);
        float4 b0 = *reinterpret_cast<const float4*>(sub + offB0);
        float4 b1 = *reinterpret_cast<const float4*>(sub + offB1);
        unsigned long long aP0 = pack2(a0.x, a0.y), aP1 = pack2(a0.z, a0.w);
        unsigned long long aP2 = pack2(a1.x, a1.y), aP3 = pack2(a1.z, a1.w);
        unsigned long long bP0 = pack2(b0.x, b0.y), bP1 = pack2(b0.z, b0.w);
        unsigned long long bP2 = pack2(b1.x, b1.y), bP3 = pack2(b1.z, b1.w);

        const int wcol = s * 16 + w * 2;         // float4 index into W row
        #pragma unroll
        for (int e = 0; e < NEXP; e++) {
            float4 wv0 = __ldg(&W4[e * (DIM / 4) + wcol]);
            float4 wv1 = __ldg(&W4[e * (DIM / 4) + wcol + 1]);
            unsigned long long w0 = pack2(wv0.x, wv0.y), w1 = pack2(wv0.z, wv0.w);
            unsigned long long w2 = pack2(wv1.x, wv1.y), w3 = pack2(wv1.z, wv1.w);
            accA[e] = ffma2(aP0, w0, accA[e]);
            accA[e] = ffma2(aP1, w1, accA[e]);
            accA[e] = ffma2(aP2, w2, accA[e]);
            accA[e] = ffma2(aP3, w3, accA[e]);
            accB[e] = ffma2(bP0, w0, accB[e]);
            accB[e] = ffma2(bP1, w1, accB[e]);
            accB[e] = ffma2(bP2, w2, accB[e]);
            accB[e] = ffma2(bP3, w3, accB[e]);
        }
        mbar_arrive(emptyBar0 + bi * 16);
    }
    __syncthreads();

    // per-lane partial logits -> smem (row stride 9 words: conflict-free)
    {
        float* lrowA = logitsBuf + (w * TILE_T + lane) * 9;
        float* lrowB = logitsBuf + (w * TILE_T + lane + 32) * 9;
        #pragma unroll
        for (int e = 0; e < NEXP; e++) {
            float2 tA = unpack2(accA[e]);
            float2 tB = unpack2(accB[e]);
            lrowA[e] = tA.x + tA.y;
            lrowB[e] = tB.x + tB.y;
        }
    }
    __syncthreads();

    if (w == 0) {
        float impLoc[NEXP];
        #pragma unroll
        for (int e = 0; e < NEXP; e++) impLoc[e] = 0.0f;
        int top1[2];

        #pragma unroll
        for (int half_t = 0; half_t < 2; half_t++) {
            const int tloc = lane + half_t * 32;
            float lg[NEXP];
            #pragma unroll
            for (int e = 0; e < NEXP; e++) {
                float sum = 0.0f;
                #pragma unroll
                for (int ww = 0; ww < WARPS; ww++)
                    sum += logitsBuf[(ww * TILE_T + tloc) * 9 + e];
                lg[e] = sum;
            }
            float m = lg[0];
            #pragma unroll
            for (int e = 1; e < NEXP; e++) m = fmaxf(m, lg[e]);
            float p[NEXP], psum = 0.0f;
            #pragma unroll
            for (int e = 0; e < NEXP; e++) { p[e] = __expf(lg[e] - m); psum += p[e]; }
            float inv = 1.0f / psum;
            #pragma unroll
            for (int e = 0; e < NEXP; e++) { p[e] *= inv; impLoc[e] += p[e]; }

            int e0 = 0; float v0 = p[0];
            #pragma unroll
            for (int e = 1; e < NEXP; e++) if (p[e] > v0) { v0 = p[e]; e0 = e; }
            int e1 = (e0 == 0) ? 1 : 0; float v1 = p[e1];
            #pragma unroll
            for (int e = 0; e < NEXP; e++)
                if (e != e0 && p[e] > v1) { v1 = p[e]; e1 = e; }
            top1[half_t] = e0;

            float rs = 1.0f / (v0 + v1);
            const int tok = tok0 + tloc;
            out[tok * 2 + 0] = v0 * rs;
            out[tok * 2 + 1] = v1 * rs;
            out[half + tok * 2 + 0] = (float)e0;
            out[half + tok * 2 + 1] = (float)e1;
        }

        #pragma unroll
        for (int e = 0; e < NEXP; e++) {
            float v = impLoc[e];
            #pragma unroll
            for (int o = 16; o; o >>= 1) v += __shfl_xor_sync(0xffffffffu, v, o);
            unsigned bal0 = __ballot_sync(0xffffffffu, top1[0] == e);
            unsigned bal1 = __ballot_sync(0xffffffffu, top1[1] == e);
            if (lane == 0) {
                g_imp_part[blockIdx.x * NEXP + e]  = v;
                g_load_part[blockIdx.x * NEXP + e] = (float)(__popc(bal0) + __popc(bal1));
            }
        }
        __threadfence();

        unsigned old = 0;
        if (lane == 0) old = atomicAdd(&g_ticket, 1u);
        old = __shfl_sync(0xffffffffu, old, 0);
        if (old == gridDim.x - 1) {
            __threadfence();
            const int e = lane & 7;
            const int q = lane >> 3;
            const int per = gridDim.x / 4;
            float si = 0.0f, sl = 0.0f;
            for (int b = q * per; b < (q + 1) * per; b++) {
                si += __ldcg(&g_imp_part[b * NEXP + e]);
                sl += __ldcg(&g_load_part[b * NEXP + e]);
            }
            si += __shfl_xor_sync(0xffffffffu, si, 8);
            si += __shfl_xor_sync(0xffffffffu, si, 16);
            sl += __shfl_xor_sync(0xffffffffu, sl, 8);
            sl += __shfl_xor_sync(0xffffffffu, sl, 16);
            float invN = 1.0f / (float)ntok;
            float prod = (si * invN) * (sl * invN);
            prod += __shfl_xor_sync(0xffffffffu, prod, 1);
            prod += __shfl_xor_sync(0xffffffffu, prod, 2);
            prod += __shfl_xor_sync(0xffffffffu, prod, 4);
            if (lane == 0) {
                out[auxPos] = (float)NEXP * prod * MOE_COEFF;
                g_ticket = 0;
            }
        }
    }
}

typedef CUresult (*PFN_encodeTiled)(
    CUtensorMap*, CUtensorMapDataType, cuuint32_t, void*,
    const cuuint64_t*, const cuuint64_t*, const cuuint32_t*, const cuuint32_t*,
    CUtensorMapInterleave, CUtensorMapSwizzle, CUtensorMapL2promotion,
    CUtensorMapFloatOOBfill);

extern "C" void kernel_launch(void* const* d_in, const int* in_sizes, int n_in,
                              void* d_out, int out_size) {
    const float* x = (const float*)d_in[0];
    const float* W = (const float*)d_in[1];
    float* out = (float*)d_out;

    const int ntok = in_sizes[0] / DIM;          // 16384
    const int half = (out_size - 1) / 2;         // 32768
    const int grid = ntok / TILE_T;              // 256

    static PFN_encodeTiled encode = nullptr;
    static bool attrDone = false;
    if (!attrDone) {
        cudaFuncSetAttribute(gate_kernel,
                             cudaFuncAttributeMaxDynamicSharedMemorySize, SMEM_TOTAL);
        void* p = nullptr;
        cudaDriverEntryPointQueryResult st;
        cudaGetDriverEntryPointByVersion("cuTensorMapEncodeTiled", &p, 12000,
                                         cudaEnableDefault, &st);
        encode = (PFN_encodeTiled)p;
        attrDone = true;
    }

    CUtensorMap tmap;
    cuuint64_t dims[2]    = {(cuuint64_t)DIM, (cuuint64_t)ntok};
    cuuint64_t strides[1] = {(cuuint64_t)DIM * 4};
    cuuint32_t box[2]     = {32, TILE_T};        // 128 B x 64 rows, SW128
    cuuint32_t es[2]      = {1, 1};
    encode(&tmap, CU_TENSOR_MAP_DATA_TYPE_FLOAT32, 2, (void*)x,
           dims, strides, box, es,
           CU_TENSOR_MAP_INTERLEAVE_NONE, CU_TENSOR_MAP_SWIZZLE_128B,
           CU_TENSOR_MAP_L2_PROMOTION_L2_128B, CU_TENSOR_MAP_FLOAT_OOB_FILL_NONE);

    gate_kernel<<<grid, THREADS, SMEM_TOTAL>>>(tmap, W, out, half, ntok,
                                               out_size - 1);
}

// round 6
// speedup vs baseline: 1.0573x; 1.0573x over previous
#include <cuda_runtime.h>
#include <cstdint>

#define DIM         2048
#define NEXP        8
#define TILE_T      64                 // tokens per block (2 per lane)
#define WARPS       4
#define THREADS     (WARPS * 32)       // 128
#define COLS_PER_WARP (DIM / WARPS)    // 512
#define STAGE_COLS  32                 // 128 B per row per stage
#define NSTAGES     (COLS_PER_WARP / STAGE_COLS)  // 16
#define NBUF        3
#define STAGE_BYTES (TILE_T * STAGE_COLS * 4)     // 8192
#define WARP_SMEM   (NBUF * STAGE_BYTES)          // 24576
#define SMEM_TOTAL  (WARPS * WARP_SMEM)           // 98304
#define MOE_COEFF   0.01f
#define MAX_BLOCKS  1024

__device__ float        g_imp_part[MAX_BLOCKS * NEXP];
__device__ float        g_load_part[MAX_BLOCKS * NEXP];
__device__ unsigned int g_ticket = 0;

__device__ __forceinline__ unsigned long long ffma2(unsigned long long a,
                                                    unsigned long long b,
                                                    unsigned long long c) {
    unsigned long long d;
    asm("fma.rn.f32x2 %0, %1, %2, %3;" : "=l"(d) : "l"(a), "l"(b), "l"(c));
    return d;
}
__device__ __forceinline__ unsigned long long pack2(float x, float y) {
    unsigned long long d;
    asm("mov.b64 %0, {%1, %2};" : "=l"(d) : "f"(x), "f"(y));
    return d;
}
__device__ __forceinline__ float2 unpack2(unsigned long long d) {
    float2 r;
    asm("mov.b64 {%0, %1}, %2;" : "=f"(r.x), "=f"(r.y) : "l"(d));
    return r;
}

__global__ void __launch_bounds__(THREADS)
gate_kernel(const float* __restrict__ x, const float* __restrict__ W,
            float* __restrict__ out, int half, int ntok, int auxPos) {
    extern __shared__ char smem[];
    float* logitsBuf = reinterpret_cast<float*>(smem);   // union over staging

    const int tid  = threadIdx.x;
    const int w    = tid >> 5;
    const int lane = tid & 31;
    const int tok0 = blockIdx.x * TILE_T;
    const int colBase = w * COLS_PER_WARP;

    char* warpBuf = smem + w * WARP_SMEM;
    const unsigned int warpBase =
        (unsigned int)__cvta_generic_to_shared(warpBuf);

    const int c_st  = lane & 7;     // chunk (float4) within 128 B row
    const int r0_st = lane >> 3;    // base row 0..3 (4 rows per LDGSTS wave)

    // ---- stage t: 64 rows x 32 cols (128 B/row), 16 LDGSTS per lane ----
    #define ISSUE_STAGE(t)                                                      \
    {                                                                           \
        const int bi_ = (t) % NBUF;                                             \
        const unsigned int base_ = warpBase + bi_ * STAGE_BYTES;                \
        const float* src0_ = x + (size_t)(tok0 + r0_st) * DIM                   \
                               + colBase + (t) * STAGE_COLS + c_st * 4;         \
        _Pragma("unroll")                                                       \
        for (int j = 0; j < 16; j++) {                                          \
            const int r_ = r0_st + j * 4;                                       \
            const unsigned int dst_ =                                           \
                base_ + r_ * 128 + ((c_st ^ (r_ & 7)) * 16);                    \
            asm volatile("cp.async.cg.shared.global [%0], [%1], 16;"            \
                         :: "r"(dst_), "l"(src0_ + (size_t)j * 4 * DIM));       \
        }                                                                       \
        asm volatile("cp.async.commit_group;");                                 \
    }

    unsigned long long accA[NEXP], accB[NEXP];
    #pragma unroll
    for (int e = 0; e < NEXP; e++) { accA[e] = 0ULL; accB[e] = 0ULL; }

    ISSUE_STAGE(0); ISSUE_STAGE(1); ISSUE_STAGE(2);

    const float4* W4 = reinterpret_cast<const float4*>(W);
    const int xorA = lane & 7;                 // (lane+32)&7 == lane&7
    const int rowOffA = lane * 128;
    const int rowOffB = (lane + 32) * 128;

    #pragma unroll 1
    for (int s = 0; s < NSTAGES; s++) {
        asm volatile("cp.async.wait_group 2;");   // group s complete
        __syncwarp();
        const int bi = s % NBUF;
        const char* buf = warpBuf + bi * STAGE_BYTES;
        const int wcol = w * (COLS_PER_WARP / 4) + s * (STAGE_COLS / 4);
        #pragma unroll
        for (int c = 0; c < STAGE_COLS / 4; c++) {      // 8 chunks
            const int co = (c ^ xorA) * 16;
            float4 xa = *reinterpret_cast<const float4*>(buf + rowOffA + co);
            float4 xb = *reinterpret_cast<const float4*>(buf + rowOffB + co);
            unsigned long long aLo = pack2(xa.x, xa.y), aHi = pack2(xa.z, xa.w);
            unsigned long long bLo = pack2(xb.x, xb.y), bHi = pack2(xb.z, xb.w);
            #pragma unroll
            for (int e = 0; e < NEXP; e++) {
                float4 wv = __ldg(&W4[e * (DIM / 4) + wcol + c]);
                unsigned long long w0 = pack2(wv.x, wv.y);
                unsigned long long w1 = pack2(wv.z, wv.w);
                accA[e] = ffma2(aLo, w0, accA[e]);
                accA[e] = ffma2(aHi, w1, accA[e]);
                accB[e] = ffma2(bLo, w0, accB[e]);
                accB[e] = ffma2(bHi, w1, accB[e]);
            }
        }
        __syncwarp();
        if (s + NBUF < NSTAGES) {
            ISSUE_STAGE(s + NBUF);          // overwrites buffer bi (just consumed)
        } else {
            asm volatile("cp.async.commit_group;");   // keep group count exact
        }
    }

    asm volatile("cp.async.wait_group 0;");
    __syncthreads();

    // per-lane partial logits -> smem (row stride 9 words: conflict-free)
    {
        float* lrowA = logitsBuf + (w * TILE_T + lane) * 9;
        float* lrowB = logitsBuf + (w * TILE_T + lane + 32) * 9;
        #pragma unroll
        for (int e = 0; e < NEXP; e++) {
            float2 tA = unpack2(accA[e]);
            float2 tB = unpack2(accB[e]);
            lrowA[e] = tA.x + tA.y;
            lrowB[e] = tB.x + tB.y;
        }
    }
    __syncthreads();

    if (w == 0) {
        float impLoc[NEXP];
        #pragma unroll
        for (int e = 0; e < NEXP; e++) impLoc[e] = 0.0f;
        int top1[2];

        #pragma unroll
        for (int half_t = 0; half_t < 2; half_t++) {
            const int tloc = lane + half_t * 32;
            float lg[NEXP];
            #pragma unroll
            for (int e = 0; e < NEXP; e++) {
                float sum = 0.0f;
                #pragma unroll
                for (int ww = 0; ww < WARPS; ww++)
                    sum += logitsBuf[(ww * TILE_T + tloc) * 9 + e];
                lg[e] = sum;
            }
            float m = lg[0];
            #pragma unroll
            for (int e = 1; e < NEXP; e++) m = fmaxf(m, lg[e]);
            float p[NEXP], psum = 0.0f;
            #pragma unroll
            for (int e = 0; e < NEXP; e++) { p[e] = __expf(lg[e] - m); psum += p[e]; }
            float inv = 1.0f / psum;
            #pragma unroll
            for (int e = 0; e < NEXP; e++) { p[e] *= inv; impLoc[e] += p[e]; }

            // top-1 / top-2 (first max wins: matches jax tie rule)
            int e0 = 0; float v0 = p[0];
            #pragma unroll
            for (int e = 1; e < NEXP; e++) if (p[e] > v0) { v0 = p[e]; e0 = e; }
            int e1 = (e0 == 0) ? 1 : 0; float v1 = p[e1];
            #pragma unroll
            for (int e = 0; e < NEXP; e++)
                if (e != e0 && p[e] > v1) { v1 = p[e]; e1 = e; }
            top1[half_t] = e0;

            float rs = 1.0f / (v0 + v1);
            const int tok = tok0 + tloc;
            out[tok * 2 + 0] = v0 * rs;
            out[tok * 2 + 1] = v1 * rs;
            out[half + tok * 2 + 0] = (float)e0;
            out[half + tok * 2 + 1] = (float)e1;
        }

        // per-block aux statistics -> scratch
        #pragma unroll
        for (int e = 0; e < NEXP; e++) {
            float v = impLoc[e];
            #pragma unroll
            for (int o = 16; o; o >>= 1) v += __shfl_xor_sync(0xffffffffu, v, o);
            unsigned bal0 = __ballot_sync(0xffffffffu, top1[0] == e);
            unsigned bal1 = __ballot_sync(0xffffffffu, top1[1] == e);
            if (lane == 0) {
                g_imp_part[blockIdx.x * NEXP + e]  = v;
                g_load_part[blockIdx.x * NEXP + e] = (float)(__popc(bal0) + __popc(bal1));
            }
        }
        __threadfence();

        // last-block finalize (ticket resets itself each graph replay)
        unsigned old = 0;
        if (lane == 0) old = atomicAdd(&g_ticket, 1u);
        old = __shfl_sync(0xffffffffu, old, 0);
        if (old == gridDim.x - 1) {
            __threadfence();
            const int e = lane & 7;
            const int q = lane >> 3;
            const int per = gridDim.x / 4;
            float si = 0.0f, sl = 0.0f;
            for (int b = q * per; b < (q + 1) * per; b++) {
                si += __ldcg(&g_imp_part[b * NEXP + e]);
                sl += __ldcg(&g_load_part[b * NEXP + e]);
            }
            si += __shfl_xor_sync(0xffffffffu, si, 8);
            si += __shfl_xor_sync(0xffffffffu, si, 16);
            sl += __shfl_xor_sync(0xffffffffu, sl, 8);
            sl += __shfl_xor_sync(0xffffffffu, sl, 16);
            float invN = 1.0f / (float)ntok;
            float prod = (si * invN) * (sl * invN);
            prod += __shfl_xor_sync(0xffffffffu, prod, 1);
            prod += __shfl_xor_sync(0xffffffffu, prod, 2);
            prod += __shfl_xor_sync(0xffffffffu, prod, 4);
            if (lane == 0) {
                out[auxPos] = (float)NEXP * prod * MOE_COEFF;
                g_ticket = 0;
            }
        }
    }
}

extern "C" void kernel_launch(void* const* d_in, const int* in_sizes, int n_in,
                              void* d_out, int out_size) {
    const float* x = (const float*)d_in[0];
    const float* W = (const float*)d_in[1];
    float* out = (float*)d_out;

    const int ntok = in_sizes[0] / DIM;          // 16384
    const int half = (out_size - 1) / 2;         // 32768
    const int grid = ntok / TILE_T;              // 256

    static bool attrDone = false;
    if (!attrDone) {
        cudaFuncSetAttribute(gate_kernel,
                             cudaFuncAttributeMaxDynamicSharedMemorySize, SMEM_TOTAL);
        attrDone = true;
    }

    gate_kernel<<<grid, THREADS, SMEM_TOTAL>>>(x, W, out, half, ntok,
                                               out_size - 1);
}

// round 7
// speedup vs baseline: 1.3638x; 1.2899x over previous
#include <cuda_runtime.h>
#include <cstdint>

#define DIM         2048
#define NEXP        8
#define TILE_T      32                 // tokens per block (1 per lane)
#define WARPS       8
#define THREADS     (WARPS * 32)       // 256
#define COLS_PER_WARP (DIM / WARPS)    // 256
#define STAGE_COLS  32                 // 128 B per token-row per stage
#define NSTAGES     (COLS_PER_WARP / STAGE_COLS)  // 8
#define NBUF        3
#define STAGE_BYTES (TILE_T * STAGE_COLS * 4)     // 4096
#define WARP_SMEM   (NBUF * STAGE_BYTES)          // 12288
#define SMEM_TOTAL  (WARPS * WARP_SMEM)           // 98304
#define MOE_COEFF   0.01f
#define MAX_BLOCKS  1024

__device__ float        g_imp_part[MAX_BLOCKS * NEXP];
__device__ float        g_load_part[MAX_BLOCKS * NEXP];
__device__ unsigned int g_ticket = 0;

__device__ __forceinline__ unsigned long long ffma2(unsigned long long a,
                                                    unsigned long long b,
                                                    unsigned long long c) {
    unsigned long long d;
    asm("fma.rn.f32x2 %0, %1, %2, %3;" : "=l"(d) : "l"(a), "l"(b), "l"(c));
    return d;
}
__device__ __forceinline__ unsigned long long pack2(float x, float y) {
    unsigned long long d;
    asm("mov.b64 %0, {%1, %2};" : "=l"(d) : "f"(x), "f"(y));
    return d;
}
__device__ __forceinline__ float2 unpack2(unsigned long long d) {
    float2 r;
    asm("mov.b64 {%0, %1}, %2;" : "=f"(r.x), "=f"(r.y) : "l"(d));
    return r;
}

__global__ void __launch_bounds__(THREADS)
gate_kernel(const float* __restrict__ x, const float* __restrict__ W,
            float* __restrict__ out, int half, int ntok, int auxPos) {
    extern __shared__ char smem[];
    float* logitsBuf = reinterpret_cast<float*>(smem);   // union over staging

    const int tid  = threadIdx.x;
    const int w    = tid >> 5;
    const int lane = tid & 31;
    const int tok0 = blockIdx.x * TILE_T;
    const int colBase = w * COLS_PER_WARP;

    char* warpBuf = smem + w * WARP_SMEM;
    const unsigned int warpBase =
        (unsigned int)__cvta_generic_to_shared(warpBuf);

    const int c_st  = lane & 7;     // float4 chunk within 128 B row
    const int r0_st = lane >> 3;    // base row 0..3

    // ---- stage t: 32 rows x 32 cols (128 B/row, full-line LDGSTS) ----
    #define ISSUE_STAGE(t)                                                      \
    {                                                                           \
        const int bi_ = (t) % NBUF;                                             \
        const unsigned int base_ = warpBase + bi_ * STAGE_BYTES;                \
        const float* src0_ = x + (size_t)(tok0 + r0_st) * DIM                   \
                               + colBase + (t) * STAGE_COLS + c_st * 4;         \
        _Pragma("unroll")                                                       \
        for (int j = 0; j < 8; j++) {                                           \
            const int r_ = r0_st + j * 4;                                       \
            const unsigned int dst_ =                                           \
                base_ + r_ * 128 + ((c_st ^ (r_ & 7)) * 16);                    \
            asm volatile("cp.async.cg.shared.global [%0], [%1], 16;"            \
                         :: "r"(dst_), "l"(src0_ + (size_t)j * 4 * DIM));       \
        }                                                                       \
        asm volatile("cp.async.commit_group;");                                 \
    }

    unsigned long long acc[NEXP];
    #pragma unroll
    for (int e = 0; e < NEXP; e++) acc[e] = 0ULL;

    ISSUE_STAGE(0); ISSUE_STAGE(1); ISSUE_STAGE(2);

    const float4* W4 = reinterpret_cast<const float4*>(W);
    const int swz = lane & 7;
    const int rowOff = lane * 128;

    #pragma unroll 1
    for (int s = 0; s < NSTAGES; s++) {
        asm volatile("cp.async.wait_group 2;");   // group s complete
        __syncwarp();
        const int bi = s % NBUF;
        const char* buf = warpBuf + bi * STAGE_BYTES;
        const int wcol = (colBase >> 2) + s * (STAGE_COLS / 4);
        #pragma unroll
        for (int c = 0; c < STAGE_COLS / 4; c++) {      // 8 chunks
            const int co = (c ^ swz) * 16;
            float4 xv = *reinterpret_cast<const float4*>(buf + rowOff + co);
            unsigned long long xLo = pack2(xv.x, xv.y);
            unsigned long long xHi = pack2(xv.z, xv.w);
            #pragma unroll
            for (int e = 0; e < NEXP; e++) {
                float4 wv = __ldg(&W4[e * (DIM / 4) + wcol + c]);
                acc[e] = ffma2(xLo, pack2(wv.x, wv.y), acc[e]);
                acc[e] = ffma2(xHi, pack2(wv.z, wv.w), acc[e]);
            }
        }
        __syncwarp();
        if (s + NBUF < NSTAGES) {
            ISSUE_STAGE(s + NBUF);          // refills buffer just consumed
        } else {
            asm volatile("cp.async.commit_group;");   // keep group count exact
        }
    }

    asm volatile("cp.async.wait_group 0;");
    __syncthreads();

    // per-lane partial logits -> smem (row stride 9 words: conflict-free)
    {
        float* lrow = logitsBuf + (w * TILE_T + lane) * 9;
        #pragma unroll
        for (int e = 0; e < NEXP; e++) {
            float2 t = unpack2(acc[e]);
            lrow[e] = t.x + t.y;
        }
    }
    __syncthreads();

    if (w == 0) {
        // lane = token within tile; sum the 8 column-strip partials
        float lg[NEXP];
        #pragma unroll
        for (int e = 0; e < NEXP; e++) {
            float sum = 0.0f;
            #pragma unroll
            for (int ww = 0; ww < WARPS; ww++)
                sum += logitsBuf[(ww * TILE_T + lane) * 9 + e];
            lg[e] = sum;
        }
        // softmax over 8
        float m = lg[0];
        #pragma unroll
        for (int e = 1; e < NEXP; e++) m = fmaxf(m, lg[e]);
        float p[NEXP], psum = 0.0f;
        #pragma unroll
        for (int e = 0; e < NEXP; e++) { p[e] = __expf(lg[e] - m); psum += p[e]; }
        float inv = 1.0f / psum;
        #pragma unroll
        for (int e = 0; e < NEXP; e++) p[e] *= inv;

        // top-1 / top-2 (first max wins: matches jax tie rule)
        int e0 = 0; float v0 = p[0];
        #pragma unroll
        for (int e = 1; e < NEXP; e++) if (p[e] > v0) { v0 = p[e]; e0 = e; }
        int e1 = (e0 == 0) ? 1 : 0; float v1 = p[e1];
        #pragma unroll
        for (int e = 0; e < NEXP; e++)
            if (e != e0 && p[e] > v1) { v1 = p[e]; e1 = e; }

        float rs = 1.0f / (v0 + v1);
        const int tok = tok0 + lane;
        out[tok * 2 + 0] = v0 * rs;
        out[tok * 2 + 1] = v1 * rs;
        out[half + tok * 2 + 0] = (float)e0;
        out[half + tok * 2 + 1] = (float)e1;

        // per-block aux statistics -> scratch
        #pragma unroll
        for (int e = 0; e < NEXP; e++) {
            float v = p[e];
            #pragma unroll
            for (int o = 16; o; o >>= 1) v += __shfl_xor_sync(0xffffffffu, v, o);
            unsigned bal = __ballot_sync(0xffffffffu, e0 == e);
            if (lane == 0) {
                g_imp_part[blockIdx.x * NEXP + e]  = v;
                g_load_part[blockIdx.x * NEXP + e] = (float)__popc(bal);
            }
        }
        __threadfence();

        // last-block finalize (ticket resets itself each graph replay)
        unsigned old = 0;
        if (lane == 0) old = atomicAdd(&g_ticket, 1u);
        old = __shfl_sync(0xffffffffu, old, 0);
        if (old == gridDim.x - 1) {
            __threadfence();
            const int e = lane & 7;
            const int q = lane >> 3;
            const int per = gridDim.x / 4;
            float si = 0.0f, sl = 0.0f;
            for (int b = q * per; b < (q + 1) * per; b++) {
                si += __ldcg(&g_imp_part[b * NEXP + e]);
                sl += __ldcg(&g_load_part[b * NEXP + e]);
            }
            si += __shfl_xor_sync(0xffffffffu, si, 8);
            si += __shfl_xor_sync(0xffffffffu, si, 16);
            sl += __shfl_xor_sync(0xffffffffu, sl, 8);
            sl += __shfl_xor_sync(0xffffffffu, sl, 16);
            float invN = 1.0f / (float)ntok;
            float prod = (si * invN) * (sl * invN);
            prod += __shfl_xor_sync(0xffffffffu, prod, 1);
            prod += __shfl_xor_sync(0xffffffffu, prod, 2);
            prod += __shfl_xor_sync(0xffffffffu, prod, 4);
            if (lane == 0) {
                out[auxPos] = (float)NEXP * prod * MOE_COEFF;
                g_ticket = 0;
            }
        }
    }
}

extern "C" void kernel_launch(void* const* d_in, const int* in_sizes, int n_in,
                              void* d_out, int out_size) {
    const float* x = (const float*)d_in[0];
    const float* W = (const float*)d_in[1];
    float* out = (float*)d_out;

    const int ntok = in_sizes[0] / DIM;          // 16384
    const int half = (out_size - 1) / 2;         // 32768
    const int grid = ntok / TILE_T;              // 512

    static bool attrDone = false;
    if (!attrDone) {
        cudaFuncSetAttribute(gate_kernel,
                             cudaFuncAttributeMaxDynamicSharedMemorySize, SMEM_TOTAL);
        attrDone = true;
    }

    gate_kernel<<<grid, THREADS, SMEM_TOTAL>>>(x, W, out, half, ntok,
                                               out_size - 1);
}

// round 8
// speedup vs baseline: 1.7237x; 1.2639x over previous
#include <cuda_runtime.h>
#include <cstdint>

#define DIM         2048
#define NEXP        8
#define TILE_T      64                  // tokens per block (2 per lane)
#define WARPS       16
#define THREADS     (WARPS * 32)        // 512
#define NPAIRS      (WARPS / 2)         // 8
#define PAIR_COLS   (DIM / NPAIRS)      // 256
#define STAGE_COLS  16                  // 64 B per token-row per stage (per pair)
#define NSTAGES     (PAIR_COLS / STAGE_COLS)  // 16
#define NBUF        3
#define PAIR_STAGE  (TILE_T * STAGE_COLS * 4) // 4096
#define PAIR_SMEM   (NBUF * PAIR_STAGE)       // 12288
#define SMEM_TOTAL  (NPAIRS * PAIR_SMEM)      // 98304
#define MOE_COEFF   0.01f
#define MAX_BLOCKS  1024

__device__ float        g_imp_part[MAX_BLOCKS * NEXP];
__device__ float        g_load_part[MAX_BLOCKS * NEXP];
__device__ unsigned int g_ticket = 0;

__device__ __forceinline__ unsigned long long ffma2(unsigned long long a,
                                                    unsigned long long b,
                                                    unsigned long long c) {
    unsigned long long d;
    asm("fma.rn.f32x2 %0, %1, %2, %3;" : "=l"(d) : "l"(a), "l"(b), "l"(c));
    return d;
}
__device__ __forceinline__ unsigned long long pack2(float x, float y) {
    unsigned long long d;
    asm("mov.b64 %0, {%1, %2};" : "=l"(d) : "f"(x), "f"(y));
    return d;
}
__device__ __forceinline__ float2 unpack2(unsigned long long d) {
    float2 r;
    asm("mov.b64 {%0, %1}, %2;" : "=f"(r.x), "=f"(r.y) : "l"(d));
    return r;
}
__device__ __forceinline__ void pair_bar(int id) {
    asm volatile("bar.sync %0, 64;" :: "r"(id) : "memory");
}

__global__ void __launch_bounds__(THREADS, 2)
gate_kernel(const float* __restrict__ x, const float* __restrict__ W,
            float* __restrict__ out, int half, int ntok, int auxPos) {
    extern __shared__ char smem[];
    float* logitsBuf = reinterpret_cast<float*>(smem);   // union over staging

    const int tid  = threadIdx.x;
    const int w    = tid >> 5;
    const int lane = tid & 31;
    const int pair = w >> 1;          // 0..7
    const int par  = w & 1;           // warp parity within pair
    const int tok0 = blockIdx.x * TILE_T;

    char* pairBuf = smem + pair * PAIR_SMEM;
    const unsigned int pairBase =
        (unsigned int)__cvta_generic_to_shared(pairBuf);

    const int c_st  = lane & 3;       // float4 piece within 64 B row
    const int r0_st = lane >> 2;      // base row 0..7

    // warp stages rows [par*32, par*32+32) of the pair's 64-row x 16-col stage
    #define ISSUE_STAGE(t)                                                      \
    {                                                                           \
        const int bi_ = (t) % NBUF;                                             \
        const unsigned int base_ = pairBase + bi_ * PAIR_STAGE;                 \
        const float* src0_ = x + (size_t)(tok0 + par * 32 + r0_st) * DIM        \
                               + pair * PAIR_COLS + (t) * STAGE_COLS + c_st * 4;\
        _Pragma("unroll")                                                       \
        for (int j = 0; j < 4; j++) {                                           \
            const int r_ = par * 32 + r0_st + j * 8;                            \
            const unsigned int dst_ =                                           \
                base_ + r_ * 64 + ((c_st ^ (r_ & 3)) * 16);                     \
            asm volatile("cp.async.cg.shared.global [%0], [%1], 16;"            \
                         :: "r"(dst_), "l"(src0_ + (size_t)j * 8 * DIM));       \
        }                                                                       \
        asm volatile("cp.async.commit_group;");                                 \
    }

    unsigned long long accA[NEXP], accB[NEXP];
    #pragma unroll
    for (int e = 0; e < NEXP; e++) { accA[e] = 0ULL; accB[e] = 0ULL; }

    ISSUE_STAGE(0); ISSUE_STAGE(1);

    const float4* W4 = reinterpret_cast<const float4*>(W);
    const int swzA = lane & 3;        // (lane+32)&3 == lane&3
    const int rowA = lane * 64;
    const int rowB = (lane + 32) * 64;
    const int barId = pair + 1;       // barrier 0 reserved for __syncthreads

    #pragma unroll 1
    for (int s = 0; s < NSTAGES; s++) {
        asm volatile("cp.async.wait_group 1;");   // own half of stage s landed
        pair_bar(barId);                          // partner's half landed too
        if (s + 2 < NSTAGES) {
            ISSUE_STAGE(s + 2);                   // buffer (s+2)%3 free (computed s-1)
        } else {
            asm volatile("cp.async.commit_group;");
        }
        const char* buf = pairBuf + (s % NBUF) * PAIR_STAGE;
        // warp computes pieces par*2, par*2+1 (cols par*8..par*8+7) for all 64 tokens
        const int wcol = pair * (PAIR_COLS / 4) + s * (STAGE_COLS / 4) + par * 2;
        #pragma unroll
        for (int i = 0; i < 2; i++) {
            const int pc = (par * 2 + i) ^ swzA;
            float4 xa = *reinterpret_cast<const float4*>(buf + rowA + pc * 16);
            float4 xb = *reinterpret_cast<const float4*>(buf + rowB + pc * 16);
            unsigned long long aLo = pack2(xa.x, xa.y), aHi = pack2(xa.z, xa.w);
            unsigned long long bLo = pack2(xb.x, xb.y), bHi = pack2(xb.z, xb.w);
            #pragma unroll
            for (int e = 0; e < NEXP; e++) {
                float4 wv = __ldg(&W4[e * (DIM / 4) + wcol + i]);
                unsigned long long w0 = pack2(wv.x, wv.y);
                unsigned long long w1 = pack2(wv.z, wv.w);
                accA[e] = ffma2(aLo, w0, accA[e]);
                accA[e] = ffma2(aHi, w1, accA[e]);
                accB[e] = ffma2(bLo, w0, accB[e]);
                accB[e] = ffma2(bHi, w1, accB[e]);
            }
        }
    }

    asm volatile("cp.async.wait_group 0;");
    __syncthreads();

    // per-lane partial logits -> smem (row stride 9 words: conflict-free)
    {
        float* lrowA = logitsBuf + (w * TILE_T + lane) * 9;
        float* lrowB = logitsBuf + (w * TILE_T + lane + 32) * 9;
        #pragma unroll
        for (int e = 0; e < NEXP; e++) {
            float2 tA = unpack2(accA[e]);
            float2 tB = unpack2(accB[e]);
            lrowA[e] = tA.x + tA.y;
            lrowB[e] = tB.x + tB.y;
        }
    }
    __syncthreads();

    if (w == 0) {
        float impLoc[NEXP];
        #pragma unroll
        for (int e = 0; e < NEXP; e++) impLoc[e] = 0.0f;
        int top1[2];

        #pragma unroll
        for (int half_t = 0; half_t < 2; half_t++) {
            const int tloc = lane + half_t * 32;
            float lg[NEXP];
            #pragma unroll
            for (int e = 0; e < NEXP; e++) {
                float sum = 0.0f;
                #pragma unroll
                for (int ww = 0; ww < WARPS; ww++)
                    sum += logitsBuf[(ww * TILE_T + tloc) * 9 + e];
                lg[e] = sum;
            }
            float m = lg[0];
            #pragma unroll
            for (int e = 1; e < NEXP; e++) m = fmaxf(m, lg[e]);
            float p[NEXP], psum = 0.0f;
            #pragma unroll
            for (int e = 0; e < NEXP; e++) { p[e] = __expf(lg[e] - m); psum += p[e]; }
            float inv = 1.0f / psum;
            #pragma unroll
            for (int e = 0; e < NEXP; e++) { p[e] *= inv; impLoc[e] += p[e]; }

            // top-1 / top-2 (first max wins: matches jax tie rule)
            int e0 = 0; float v0 = p[0];
            #pragma unroll
            for (int e = 1; e < NEXP; e++) if (p[e] > v0) { v0 = p[e]; e0 = e; }
            int e1 = (e0 == 0) ? 1 : 0; float v1 = p[e1];
            #pragma unroll
            for (int e = 0; e < NEXP; e++)
                if (e != e0 && p[e] > v1) { v1 = p[e]; e1 = e; }
            top1[half_t] = e0;

            float rs = 1.0f / (v0 + v1);
            const int tok = tok0 + tloc;
            out[tok * 2 + 0] = v0 * rs;
            out[tok * 2 + 1] = v1 * rs;
            out[half + tok * 2 + 0] = (float)e0;
            out[half + tok * 2 + 1] = (float)e1;
        }

        // per-block aux statistics -> scratch
        #pragma unroll
        for (int e = 0; e < NEXP; e++) {
            float v = impLoc[e];
            #pragma unroll
            for (int o = 16; o; o >>= 1) v += __shfl_xor_sync(0xffffffffu, v, o);
            unsigned bal0 = __ballot_sync(0xffffffffu, top1[0] == e);
            unsigned bal1 = __ballot_sync(0xffffffffu, top1[1] == e);
            if (lane == 0) {
                g_imp_part[blockIdx.x * NEXP + e]  = v;
                g_load_part[blockIdx.x * NEXP + e] = (float)(__popc(bal0) + __popc(bal1));
            }
        }
        __threadfence();

        // last-block finalize (ticket resets itself each graph replay)
        unsigned old = 0;
        if (lane == 0) old = atomicAdd(&g_ticket, 1u);
        old = __shfl_sync(0xffffffffu, old, 0);
        if (old == gridDim.x - 1) {
            __threadfence();
            const int e = lane & 7;
            const int q = lane >> 3;
            const int per = gridDim.x / 4;
            float si = 0.0f, sl = 0.0f;
            for (int b = q * per; b < (q + 1) * per; b++) {
                si += __ldcg(&g_imp_part[b * NEXP + e]);
                sl += __ldcg(&g_load_part[b * NEXP + e]);
            }
            si += __shfl_xor_sync(0xffffffffu, si, 8);
            si += __shfl_xor_sync(0xffffffffu, si, 16);
            sl += __shfl_xor_sync(0xffffffffu, sl, 8);
            sl += __shfl_xor_sync(0xffffffffu, sl, 16);
            float invN = 1.0f / (float)ntok;
            float prod = (si * invN) * (sl * invN);
            prod += __shfl_xor_sync(0xffffffffu, prod, 1);
            prod += __shfl_xor_sync(0xffffffffu, prod, 2);
            prod += __shfl_xor_sync(0xffffffffu, prod, 4);
            if (lane == 0) {
                out[auxPos] = (float)NEXP * prod * MOE_COEFF;
                g_ticket = 0;
            }
        }
    }
}

extern "C" void kernel_launch(void* const* d_in, const int* in_sizes, int n_in,
                              void* d_out, int out_size) {
    const float* x = (const float*)d_in[0];
    const float* W = (const float*)d_in[1];
    float* out = (float*)d_out;

    const int ntok = in_sizes[0] / DIM;          // 16384
    const int half = (out_size - 1) / 2;         // 32768
    const int grid = ntok / TILE_T;              // 256

    static bool attrDone = false;
    if (!attrDone) {
        cudaFuncSetAttribute(gate_kernel,
                             cudaFuncAttributeMaxDynamicSharedMemorySize, SMEM_TOTAL);
        attrDone = true;
    }

    gate_kernel<<<grid, THREADS, SMEM_TOTAL>>>(x, W, out, half, ntok,
                                               out_size - 1);
}

// round 9
// speedup vs baseline: 1.7916x; 1.0394x over previous
#include <cuda_runtime.h>
#include <cstdint>

#define DIM         2048
#define NEXP        8
#define TILE_T      64                  // tokens per block (2 per lane)
#define WARPS       16
#define THREADS     (WARPS * 32)        // 512
#define NQUADS      4                   // 4 warps share a stage buffer
#define QUAD_COLS   (DIM / NQUADS)      // 512
#define STAGE_COLS  32                  // 128 B per token-row per stage
#define NSTAGES     (QUAD_COLS / STAGE_COLS)  // 16
#define NBUF        3
#define STAGE_BYTES (TILE_T * STAGE_COLS * 4) // 8192
#define QUAD_SMEM   (NBUF * STAGE_BYTES)      // 24576
#define SMEM_TOTAL  (NQUADS * QUAD_SMEM)      // 98304
#define MOE_COEFF   0.01f
#define MAX_BLOCKS  1024

__device__ float        g_imp_part[MAX_BLOCKS * NEXP];
__device__ float        g_load_part[MAX_BLOCKS * NEXP];
__device__ unsigned int g_ticket = 0;

__device__ __forceinline__ unsigned long long ffma2(unsigned long long a,
                                                    unsigned long long b,
                                                    unsigned long long c) {
    unsigned long long d;
    asm("fma.rn.f32x2 %0, %1, %2, %3;" : "=l"(d) : "l"(a), "l"(b), "l"(c));
    return d;
}
__device__ __forceinline__ unsigned long long pack2(float x, float y) {
    unsigned long long d;
    asm("mov.b64 %0, {%1, %2};" : "=l"(d) : "f"(x), "f"(y));
    return d;
}
__device__ __forceinline__ float2 unpack2(unsigned long long d) {
    float2 r;
    asm("mov.b64 {%0, %1}, %2;" : "=f"(r.x), "=f"(r.y) : "l"(d));
    return r;
}
__device__ __forceinline__ void quad_bar(int id) {
    asm volatile("bar.sync %0, 128;" :: "r"(id) : "memory");
}

__global__ void __launch_bounds__(THREADS, 2)
gate_kernel(const float* __restrict__ x, const float* __restrict__ W,
            float* __restrict__ out, int half, int ntok, int auxPos) {
    extern __shared__ char smem[];
    float* logitsBuf = reinterpret_cast<float*>(smem);   // union over staging

    const int tid  = threadIdx.x;
    const int w    = tid >> 5;
    const int lane = tid & 31;
    const int quad = w >> 2;          // 0..3
    const int wq   = w & 3;           // warp index within quad
    const int tok0 = blockIdx.x * TILE_T;

    char* quadBuf = smem + quad * QUAD_SMEM;
    const unsigned int quadBase =
        (unsigned int)__cvta_generic_to_shared(quadBuf);

    const int c_st  = lane & 7;       // float4 chunk within 128 B row
    const int r0_st = lane >> 3;      // base row 0..3

    // warp stages rows [wq*16, wq*16+16) of the quad's 64-row x 32-col stage;
    // full 128 B lines, SW128-style chunk^row swizzle.
    #define ISSUE_STAGE(t)                                                      \
    {                                                                           \
        const int bi_ = (t) % NBUF;                                             \
        const unsigned int base_ = quadBase + bi_ * STAGE_BYTES;                \
        const float* src0_ = x + (size_t)(tok0 + wq * 16 + r0_st) * DIM         \
                               + quad * QUAD_COLS + (t) * STAGE_COLS + c_st * 4;\
        _Pragma("unroll")                                                       \
        for (int j = 0; j < 4; j++) {                                           \
            const int r_ = wq * 16 + r0_st + j * 4;                             \
            const unsigned int dst_ =                                           \
                base_ + r_ * 128 + ((c_st ^ (r_ & 7)) * 16);                    \
            asm volatile("cp.async.cg.shared.global [%0], [%1], 16;"            \
                         :: "r"(dst_), "l"(src0_ + (size_t)j * 4 * DIM));       \
        }                                                                       \
        asm volatile("cp.async.commit_group;");                                 \
    }

    unsigned long long accA[NEXP], accB[NEXP];
    #pragma unroll
    for (int e = 0; e < NEXP; e++) { accA[e] = 0ULL; accB[e] = 0ULL; }

    ISSUE_STAGE(0); ISSUE_STAGE(1);

    const float4* W4 = reinterpret_cast<const float4*>(W);
    const int swz  = lane & 7;        // (lane+32)&7 == lane&7
    const int rowA = lane * 128;
    const int rowB = (lane + 32) * 128;
    const int barId = quad + 1;       // barrier 0 reserved for __syncthreads

    #pragma unroll 1
    for (int s = 0; s < NSTAGES; s++) {
        asm volatile("cp.async.wait_group 1;");   // own share of stage s landed
        quad_bar(barId);                          // all 4 warps' shares landed
        if (s + 2 < NSTAGES) {
            ISSUE_STAGE(s + 2);       // buffer (s+2)%3 free: all computed s-1 pre-bar
        } else {
            asm volatile("cp.async.commit_group;");
        }
        const char* buf = quadBuf + (s % NBUF) * STAGE_BYTES;
        // warp computes chunks wq*2, wq*2+1 (cols wq*8..wq*8+7) for all 64 tokens
        const int wcol = quad * (QUAD_COLS / 4) + s * (STAGE_COLS / 4) + wq * 2;
        #pragma unroll
        for (int i = 0; i < 2; i++) {
            const int pc = (wq * 2 + i) ^ swz;
            float4 xa = *reinterpret_cast<const float4*>(buf + rowA + pc * 16);
            float4 xb = *reinterpret_cast<const float4*>(buf + rowB + pc * 16);
            unsigned long long aLo = pack2(xa.x, xa.y), aHi = pack2(xa.z, xa.w);
            unsigned long long bLo = pack2(xb.x, xb.y), bHi = pack2(xb.z, xb.w);
            #pragma unroll
            for (int e = 0; e < NEXP; e++) {
                float4 wv = __ldg(&W4[e * (DIM / 4) + wcol + i]);
                unsigned long long w0 = pack2(wv.x, wv.y);
                unsigned long long w1 = pack2(wv.z, wv.w);
                accA[e] = ffma2(aLo, w0, accA[e]);
                accA[e] = ffma2(aHi, w1, accA[e]);
                accB[e] = ffma2(bLo, w0, accB[e]);
                accB[e] = ffma2(bHi, w1, accB[e]);
            }
        }
    }

    asm volatile("cp.async.wait_group 0;");
    __syncthreads();

    // per-lane partial logits -> smem (row stride 9 words: conflict-free)
    {
        float* lrowA = logitsBuf + (w * TILE_T + lane) * 9;
        float* lrowB = logitsBuf + (w * TILE_T + lane + 32) * 9;
        #pragma unroll
        for (int e = 0; e < NEXP; e++) {
            float2 tA = unpack2(accA[e]);
            float2 tB = unpack2(accB[e]);
            lrowA[e] = tA.x + tA.y;
            lrowB[e] = tB.x + tB.y;
        }
    }
    __syncthreads();

    if (w == 0) {
        float impLoc[NEXP];
        #pragma unroll
        for (int e = 0; e < NEXP; e++) impLoc[e] = 0.0f;
        int top1[2];

        #pragma unroll
        for (int half_t = 0; half_t < 2; half_t++) {
            const int tloc = lane + half_t * 32;
            float lg[NEXP];
            #pragma unroll
            for (int e = 0; e < NEXP; e++) {
                float sum = 0.0f;
                #pragma unroll
                for (int ww = 0; ww < WARPS; ww++)
                    sum += logitsBuf[(ww * TILE_T + tloc) * 9 + e];
                lg[e] = sum;
            }
            float m = lg[0];
            #pragma unroll
            for (int e = 1; e < NEXP; e++) m = fmaxf(m, lg[e]);
            float p[NEXP], psum = 0.0f;
            #pragma unroll
            for (int e = 0; e < NEXP; e++) { p[e] = __expf(lg[e] - m); psum += p[e]; }
            float inv = 1.0f / psum;
            #pragma unroll
            for (int e = 0; e < NEXP; e++) { p[e] *= inv; impLoc[e] += p[e]; }

            // top-1 / top-2 (first max wins: matches jax tie rule)
            int e0 = 0; float v0 = p[0];
            #pragma unroll
            for (int e = 1; e < NEXP; e++) if (p[e] > v0) { v0 = p[e]; e0 = e; }
            int e1 = (e0 == 0) ? 1 : 0; float v1 = p[e1];
            #pragma unroll
            for (int e = 0; e < NEXP; e++)
                if (e != e0 && p[e] > v1) { v1 = p[e]; e1 = e; }
            top1[half_t] = e0;

            float rs = 1.0f / (v0 + v1);
            const int tok = tok0 + tloc;
            out[tok * 2 + 0] = v0 * rs;
            out[tok * 2 + 1] = v1 * rs;
            out[half + tok * 2 + 0] = (float)e0;
            out[half + tok * 2 + 1] = (float)e1;
        }

        // per-block aux statistics -> scratch
        #pragma unroll
        for (int e = 0; e < NEXP; e++) {
            float v = impLoc[e];
            #pragma unroll
            for (int o = 16; o; o >>= 1) v += __shfl_xor_sync(0xffffffffu, v, o);
            unsigned bal0 = __ballot_sync(0xffffffffu, top1[0] == e);
            unsigned bal1 = __ballot_sync(0xffffffffu, top1[1] == e);
            if (lane == 0) {
                g_imp_part[blockIdx.x * NEXP + e]  = v;
                g_load_part[blockIdx.x * NEXP + e] = (float)(__popc(bal0) + __popc(bal1));
            }
        }
        __threadfence();

        // last-block finalize (ticket resets itself each graph replay)
        unsigned old = 0;
        if (lane == 0) old = atomicAdd(&g_ticket, 1u);
        old = __shfl_sync(0xffffffffu, old, 0);
        if (old == gridDim.x - 1) {
            __threadfence();
            const int e = lane & 7;
            const int q = lane >> 3;
            const int per = gridDim.x / 4;
            float si = 0.0f, sl = 0.0f;
            for (int b = q * per; b < (q + 1) * per; b++) {
                si += __ldcg(&g_imp_part[b * NEXP + e]);
                sl += __ldcg(&g_load_part[b * NEXP + e]);
            }
            si += __shfl_xor_sync(0xffffffffu, si, 8);
            si += __shfl_xor_sync(0xffffffffu, si, 16);
            sl += __shfl_xor_sync(0xffffffffu, sl, 8);
            sl += __shfl_xor_sync(0xffffffffu, sl, 16);
            float invN = 1.0f / (float)ntok;
            float prod = (si * invN) * (sl * invN);
            prod += __shfl_xor_sync(0xffffffffu, prod, 1);
            prod += __shfl_xor_sync(0xffffffffu, prod, 2);
            prod += __shfl_xor_sync(0xffffffffu, prod, 4);
            if (lane == 0) {
                out[auxPos] = (float)NEXP * prod * MOE_COEFF;
                g_ticket = 0;
            }
        }
    }
}

extern "C" void kernel_launch(void* const* d_in, const int* in_sizes, int n_in,
                              void* d_out, int out_size) {
    const float* x = (const float*)d_in[0];
    const float* W = (const float*)d_in[1];
    float* out = (float*)d_out;

    const int ntok = in_sizes[0] / DIM;          // 16384
    const int half = (out_size - 1) / 2;         // 32768
    const int grid = ntok / TILE_T;              // 256

    static bool attrDone = false;
    if (!attrDone) {
        cudaFuncSetAttribute(gate_kernel,
                             cudaFuncAttributeMaxDynamicSharedMemorySize, SMEM_TOTAL);
        attrDone = true;
    }

    gate_kernel<<<grid, THREADS, SMEM_TOTAL>>>(x, W, out, half, ntok,
                                               out_size - 1);
}

// round 10
// speedup vs baseline: 1.8088x; 1.0096x over previous
#include <cuda_runtime.h>
#include <cstdint>

#define DIM         2048
#define NEXP        8
#define TILE_T      64                  // tokens per block (2 per lane)
#define WARPS       16
#define THREADS     (WARPS * 32)        // 512
#define NQUADS      4                   // 4 warps share a stage buffer
#define QUAD_COLS   (DIM / NQUADS)      // 512
#define STAGE_COLS  32                  // 128 B per token-row per stage
#define NSTAGES     (QUAD_COLS / STAGE_COLS)  // 16
#define NBUF        3
#define STAGE_BYTES (TILE_T * STAGE_COLS * 4) // 8192
#define QUAD_SMEM   (NBUF * STAGE_BYTES)      // 24576
#define SMEM_TOTAL  (NQUADS * QUAD_SMEM)      // 98304
#define MOE_COEFF   0.01f
#define MAX_BLOCKS  1024

__device__ float        g_imp_part[MAX_BLOCKS * NEXP];
__device__ float        g_load_part[MAX_BLOCKS * NEXP];
__device__ unsigned int g_ticket = 0;

__device__ __forceinline__ unsigned long long ffma2(unsigned long long a,
                                                    unsigned long long b,
                                                    unsigned long long c) {
    unsigned long long d;
    asm("fma.rn.f32x2 %0, %1, %2, %3;" : "=l"(d) : "l"(a), "l"(b), "l"(c));
    return d;
}
__device__ __forceinline__ float2 unpack2(unsigned long long d) {
    float2 r;
    asm("mov.b64 {%0, %1}, %2;" : "=f"(r.x), "=f"(r.y) : "l"(d));
    return r;
}
__device__ __forceinline__ void quad_bar(int id) {
    asm volatile("bar.sync %0, 128;" :: "r"(id) : "memory");
}

__global__ void __launch_bounds__(THREADS, 2)
gate_kernel(const float* __restrict__ x, const float* __restrict__ W,
            float* __restrict__ out, int half, int ntok, int auxPos) {
    extern __shared__ char smem[];
    float* logitsBuf = reinterpret_cast<float*>(smem);   // union over staging

    const int tid  = threadIdx.x;
    const int w    = tid >> 5;
    const int lane = tid & 31;
    const int quad = w >> 2;          // 0..3
    const int wq   = w & 3;           // warp index within quad
    const int tok0 = blockIdx.x * TILE_T;

    char* quadBuf = smem + quad * QUAD_SMEM;
    const unsigned int quadBase =
        (unsigned int)__cvta_generic_to_shared(quadBuf);

    const int c_st  = lane & 7;       // float4 chunk within 128 B row
    const int r0_st = lane >> 3;      // base row 0..3

    // warp stages rows [wq*16, wq*16+16) of the quad's 64-row x 32-col stage;
    // full 128 B lines, SW128-style chunk^row swizzle.
    #define ISSUE_STAGE(t)                                                      \
    {                                                                           \
        const int bi_ = (t) % NBUF;                                             \
        const unsigned int base_ = quadBase + bi_ * STAGE_BYTES;                \
        const float* src0_ = x + (size_t)(tok0 + wq * 16 + r0_st) * DIM         \
                               + quad * QUAD_COLS + (t) * STAGE_COLS + c_st * 4;\
        _Pragma("unroll")                                                       \
        for (int j = 0; j < 4; j++) {                                           \
            const int r_ = wq * 16 + r0_st + j * 4;                             \
            const unsigned int dst_ =                                           \
                base_ + r_ * 128 + ((c_st ^ (r_ & 7)) * 16);                    \
            asm volatile("cp.async.cg.shared.global [%0], [%1], 16;"            \
                         :: "r"(dst_), "l"(src0_ + (size_t)j * 4 * DIM));       \
        }                                                                       \
        asm volatile("cp.async.commit_group;");                                 \
    }

    unsigned long long accA[NEXP], accB[NEXP];
    #pragma unroll
    for (int e = 0; e < NEXP; e++) { accA[e] = 0ULL; accB[e] = 0ULL; }

    ISSUE_STAGE(0); ISSUE_STAGE(1);

    const ulonglong2* W2 = reinterpret_cast<const ulonglong2*>(W);
    const int swz  = lane & 7;        // (lane+32)&7 == lane&7
    const int rowA = lane * 128;
    const int rowB = (lane + 32) * 128;
    const int barId = quad + 1;       // barrier 0 reserved for __syncthreads

    #pragma unroll 1
    for (int s = 0; s < NSTAGES; s++) {
        asm volatile("cp.async.wait_group 1;");   // own share of stage s landed
        quad_bar(barId);                          // all 4 warps' shares landed
        if (s + 2 < NSTAGES) {
            ISSUE_STAGE(s + 2);       // buffer (s+2)%3 free: all computed s-1 pre-bar
        } else {
            asm volatile("cp.async.commit_group;");
        }
        const char* buf = quadBuf + (s % NBUF) * STAGE_BYTES;
        // warp computes chunks wq*2, wq*2+1 (cols wq*8..wq*8+7) for all 64 tokens
        const int wcol = quad * (QUAD_COLS / 4) + s * (STAGE_COLS / 4) + wq * 2;
        #pragma unroll
        for (int i = 0; i < 2; i++) {
            const int pc = (wq * 2 + i) ^ swz;
            // 16B loads land in aligned register pairs: .x/.y are free u64 views
            ulonglong2 xa = *reinterpret_cast<const ulonglong2*>(buf + rowA + pc * 16);
            ulonglong2 xb = *reinterpret_cast<const ulonglong2*>(buf + rowB + pc * 16);
            #pragma unroll
            for (int e = 0; e < NEXP; e++) {
                ulonglong2 wv = __ldg(&W2[e * (DIM / 4) + wcol + i]);
                accA[e] = ffma2(xa.x, wv.x, accA[e]);
                accA[e] = ffma2(xa.y, wv.y, accA[e]);
                accB[e] = ffma2(xb.x, wv.x, accB[e]);
                accB[e] = ffma2(xb.y, wv.y, accB[e]);
            }
        }
    }

    asm volatile("cp.async.wait_group 0;");
    __syncthreads();

    // per-lane partial logits -> smem (row stride 9 words: conflict-free)
    {
        float* lrowA = logitsBuf + (w * TILE_T + lane) * 9;
        float* lrowB = logitsBuf + (w * TILE_T + lane + 32) * 9;
        #pragma unroll
        for (int e = 0; e < NEXP; e++) {
            float2 tA = unpack2(accA[e]);
            float2 tB = unpack2(accB[e]);
            lrowA[e] = tA.x + tA.y;
            lrowB[e] = tB.x + tB.y;
        }
    }
    __syncthreads();

    if (w == 0) {
        float impLoc[NEXP];
        #pragma unroll
        for (int e = 0; e < NEXP; e++) impLoc[e] = 0.0f;
        int top1[2];

        #pragma unroll
        for (int half_t = 0; half_t < 2; half_t++) {
            const int tloc = lane + half_t * 32;
            float lg[NEXP];
            #pragma unroll
            for (int e = 0; e < NEXP; e++) {
                float sum = 0.0f;
                #pragma unroll
                for (int ww = 0; ww < WARPS; ww++)
                    sum += logitsBuf[(ww * TILE_T + tloc) * 9 + e];
                lg[e] = sum;
            }
            float m = lg[0];
            #pragma unroll
            for (int e = 1; e < NEXP; e++) m = fmaxf(m, lg[e]);
            float p[NEXP], psum = 0.0f;
            #pragma unroll
            for (int e = 0; e < NEXP; e++) { p[e] = __expf(lg[e] - m); psum += p[e]; }
            float inv = 1.0f / psum;
            #pragma unroll
            for (int e = 0; e < NEXP; e++) { p[e] *= inv; impLoc[e] += p[e]; }

            // top-1 / top-2 (first max wins: matches jax tie rule)
            int e0 = 0; float v0 = p[0];
            #pragma unroll
            for (int e = 1; e < NEXP; e++) if (p[e] > v0) { v0 = p[e]; e0 = e; }
            int e1 = (e0 == 0) ? 1 : 0; float v1 = p[e1];
            #pragma unroll
            for (int e = 0; e < NEXP; e++)
                if (e != e0 && p[e] > v1) { v1 = p[e]; e1 = e; }
            top1[half_t] = e0;

            float rs = 1.0f / (v0 + v1);
            const int tok = tok0 + tloc;
            out[tok * 2 + 0] = v0 * rs;
            out[tok * 2 + 1] = v1 * rs;
            out[half + tok * 2 + 0] = (float)e0;
            out[half + tok * 2 + 1] = (float)e1;
        }

        // per-block aux statistics -> scratch
        #pragma unroll
        for (int e = 0; e < NEXP; e++) {
            float v = impLoc[e];
            #pragma unroll
            for (int o = 16; o; o >>= 1) v += __shfl_xor_sync(0xffffffffu, v, o);
            unsigned bal0 = __ballot_sync(0xffffffffu, top1[0] == e);
            unsigned bal1 = __ballot_sync(0xffffffffu, top1[1] == e);
            if (lane == 0) {
                g_imp_part[blockIdx.x * NEXP + e]  = v;
                g_load_part[blockIdx.x * NEXP + e] = (float)(__popc(bal0) + __popc(bal1));
            }
        }
        __threadfence();

        // last-block finalize (ticket resets itself each graph replay)
        unsigned old = 0;
        if (lane == 0) old = atomicAdd(&g_ticket, 1u);
        old = __shfl_sync(0xffffffffu, old, 0);
        if (old == gridDim.x - 1) {
            __threadfence();
            const int e = lane & 7;
            const int q = lane >> 3;
            const int per = gridDim.x / 4;
            float si = 0.0f, sl = 0.0f;
            for (int b = q * per; b < (q + 1) * per; b++) {
                si += __ldcg(&g_imp_part[b * NEXP + e]);
                sl += __ldcg(&g_load_part[b * NEXP + e]);
            }
            si += __shfl_xor_sync(0xffffffffu, si, 8);
            si += __shfl_xor_sync(0xffffffffu, si, 16);
            sl += __shfl_xor_sync(0xffffffffu, sl, 8);
            sl += __shfl_xor_sync(0xffffffffu, sl, 16);
            float invN = 1.0f / (float)ntok;
            float prod = (si * invN) * (sl * invN);
            prod += __shfl_xor_sync(0xffffffffu, prod, 1);
            prod += __shfl_xor_sync(0xffffffffu, prod, 2);
            prod += __shfl_xor_sync(0xffffffffu, prod, 4);
            if (lane == 0) {
                out[auxPos] = (float)NEXP * prod * MOE_COEFF;
                g_ticket = 0;
            }
        }
    }
}

extern "C" void kernel_launch(void* const* d_in, const int* in_sizes, int n_in,
                              void* d_out, int out_size) {
    const float* x = (const float*)d_in[0];
    const float* W = (const float*)d_in[1];
    float* out = (float*)d_out;

    const int ntok = in_sizes[0] / DIM;          // 16384
    const int half = (out_size - 1) / 2;         // 32768
    const int grid = ntok / TILE_T;              // 256

    static bool attrDone = false;
    if (!attrDone) {
        cudaFuncSetAttribute(gate_kernel,
                             cudaFuncAttributeMaxDynamicSharedMemorySize, SMEM_TOTAL);
        attrDone = true;
    }

    gate_kernel<<<grid, THREADS, SMEM_TOTAL>>>(x, W, out, half, ntok,
                                               out_size - 1);
}